// round 1
// baseline (speedup 1.0000x reference)
#include <cuda_runtime.h>
#include <cstdint>
#include <math.h>

// Problem constants (fixed by the reference)
#define NTOK 8192      // B*S = 4*2048 tokens
#define DDIM 2048      // embed
#define HDIM 1408      // ffn intermediate
#define NEXP 8         // routed experts; slot 8 = shared expert
#define ROWCAP (9 * NTOK)   // 73728 compact rows (8 routed capacities + shared)

typedef unsigned long long u64;

// ---------------- device scratch (static, allocation-free) ----------------
__device__ int   d_cnt[16];
__device__ int   d_row_token[ROWCAP];
__device__ float d_row_w[ROWCAP];
// activation scratch: gate writes raw G, up-kernel rewrites silu(G)*U in place
__device__ float d_act[(size_t)ROWCAP * HDIM];

// ---------------- packed f32x2 helpers (sm_103a FFMA2 path) ----------------
__device__ __forceinline__ u64 pack2(float lo, float hi) {
    u64 r;
    asm("mov.b64 %0, {%1, %2};" : "=l"(r) : "f"(lo), "f"(hi));
    return r;
}
__device__ __forceinline__ u64 fma2(u64 a, u64 b, u64 c) {
    u64 d;
    asm("fma.rn.f32x2 %0, %1, %2, %3;" : "=l"(d) : "l"(a), "l"(b), "l"(c));
    return d;
}
__device__ __forceinline__ float2 unpack2(u64 v) {
    float2 f;
    asm("mov.b64 {%0, %1}, %2;" : "=f"(f.x), "=f"(f.y) : "l"(v));
    return f;
}

__device__ __forceinline__ float silu_f(float g) {
    return g / (1.f + expf(-g));
}

// ---------------- init: zero per-expert cursors (graph replays!) -----------
__global__ void init_kernel() {
    if (threadIdx.x < 16) d_cnt[threadIdx.x] = 0;
}

// ---------------- router: sigmoid top-2, build compact row lists -----------
__global__ void router_kernel(const float* __restrict__ x,
                              const float* __restrict__ Wr,
                              const float* __restrict__ br,
                              const float* __restrict__ rb) {
    int g = blockIdx.x * blockDim.x + threadIdx.x;
    int t = g >> 5;
    int lane = g & 31;
    if (t >= NTOK) return;

    const float* xr = x + (size_t)t * DDIM;
    float acc[NEXP];
#pragma unroll
    for (int e = 0; e < NEXP; e++) acc[e] = 0.f;

    for (int d = lane; d < DDIM; d += 32) {
        float xv = xr[d];
        const float* wr = Wr + d * NEXP;
#pragma unroll
        for (int e = 0; e < NEXP; e++) acc[e] += xv * wr[e];
    }
#pragma unroll
    for (int off = 16; off > 0; off >>= 1) {
#pragma unroll
        for (int e = 0; e < NEXP; e++)
            acc[e] += __shfl_xor_sync(0xffffffffu, acc[e], off);
    }
    if (lane == 0) {
        float p[NEXP];
#pragma unroll
        for (int e = 0; e < NEXP; e++)
            p[e] = 1.f / (1.f + expf(-(acc[e] + br[e] + rb[e])));
        // top-2, ties -> lowest index first (matches jax.lax.top_k)
        int i0 = 0;
#pragma unroll
        for (int e = 1; e < NEXP; e++) if (p[e] > p[i0]) i0 = e;
        int i1 = (i0 == 0) ? 1 : 0;
#pragma unroll
        for (int e = 0; e < NEXP; e++) if (e != i0 && p[e] > p[i1]) i1 = e;
        float s = p[i0] + p[i1];
        float w0 = p[i0] / s;
        float w1 = p[i1] / s;

        int r0 = atomicAdd(&d_cnt[i0], 1);
        d_row_token[i0 * NTOK + r0] = t;
        d_row_w[i0 * NTOK + r0] = w0;
        int r1 = atomicAdd(&d_cnt[i1], 1);
        d_row_token[i1 * NTOK + r1] = t;
        d_row_w[i1 * NTOK + r1] = w1;
        // shared-expert region: identity rows, weight 1
        d_row_token[NEXP * NTOK + t] = t;
        d_row_w[NEXP * NTOK + t] = 1.f;
    }
}

// ---------------- gate/up GEMM: [count x DDIM] @ [DDIM x HDIM] --------------
// fuse_silu == 0 : write raw G into d_act
// fuse_silu == 1 : read G from d_act, write silu(G) * U back in place
__global__ __launch_bounds__(256, 2)
void gu_gemm(const float* __restrict__ x,
             const float* __restrict__ Bstk,
             const float* __restrict__ Bsh,
             int fuse_silu) {
    const int e = blockIdx.z;
    const int count = (e == NEXP) ? NTOK : d_cnt[e];
    const int m0 = blockIdx.y * 128;
    if (m0 >= count) return;
    const int n0 = blockIdx.x * 128;
    const float* Bp = (e == NEXP) ? Bsh : (Bstk + (size_t)e * DDIM * HDIM);
    const int rowbase = e * NTOK + m0;

    __shared__ float As[16][132];
    __shared__ float Bs[16][128];
    __shared__ int toks[128];

    const int tid = threadIdx.x;
    if (tid < 128) toks[tid] = d_row_token[rowbase + tid];
    __syncthreads();

    const int tx = tid & 15;
    const int ty = tid >> 4;
    const int arow = tid >> 1;
    const int akp  = (tid & 1) * 8;
    const int brow = tid >> 4;
    const int bcol = (tid & 15) * 8;

    const float* xr = x + (size_t)toks[arow] * DDIM + akp;
    const float* bp = Bp + (size_t)brow * HDIM + n0 + bcol;

    u64 acc[4][8];
#pragma unroll
    for (int i = 0; i < 4; i++)
#pragma unroll
        for (int j = 0; j < 8; j++) acc[i][j] = 0ull;

    for (int k0 = 0; k0 < DDIM; k0 += 16) {
        float4 a0 = *(const float4*)(xr + k0);
        float4 a1 = *(const float4*)(xr + k0 + 4);
        float4 b0 = *(const float4*)(bp + (size_t)k0 * HDIM);
        float4 b1 = *(const float4*)(bp + (size_t)k0 * HDIM + 4);
        __syncthreads();
        As[akp + 0][arow] = a0.x; As[akp + 1][arow] = a0.y;
        As[akp + 2][arow] = a0.z; As[akp + 3][arow] = a0.w;
        As[akp + 4][arow] = a1.x; As[akp + 5][arow] = a1.y;
        As[akp + 6][arow] = a1.z; As[akp + 7][arow] = a1.w;
        *(float4*)&Bs[brow][bcol]     = b0;
        *(float4*)&Bs[brow][bcol + 4] = b1;
        __syncthreads();
#pragma unroll
        for (int kk = 0; kk < 16; kk++) {
            float4 av0 = *(const float4*)&As[kk][ty * 8];
            float4 av1 = *(const float4*)&As[kk][ty * 8 + 4];
            float4 bv0 = *(const float4*)&Bs[kk][tx * 8];
            float4 bv1 = *(const float4*)&Bs[kk][tx * 8 + 4];
            u64 ap[4] = { pack2(av0.x, av0.y), pack2(av0.z, av0.w),
                          pack2(av1.x, av1.y), pack2(av1.z, av1.w) };
            u64 bd[8] = { pack2(bv0.x, bv0.x), pack2(bv0.y, bv0.y),
                          pack2(bv0.z, bv0.z), pack2(bv0.w, bv0.w),
                          pack2(bv1.x, bv1.x), pack2(bv1.y, bv1.y),
                          pack2(bv1.z, bv1.z), pack2(bv1.w, bv1.w) };
#pragma unroll
            for (int i = 0; i < 4; i++)
#pragma unroll
                for (int j = 0; j < 8; j++)
                    acc[i][j] = fma2(ap[i], bd[j], acc[i][j]);
        }
    }

    // epilogue
#pragma unroll
    for (int i = 0; i < 4; i++) {
        float2 f[8];
#pragma unroll
        for (int j = 0; j < 8; j++) f[j] = unpack2(acc[i][j]);
#pragma unroll
        for (int h = 0; h < 2; h++) {
            int m = ty * 8 + i * 2 + h;
            size_t off = (size_t)(rowbase + m) * HDIM + n0 + tx * 8;
            float v[8];
#pragma unroll
            for (int j = 0; j < 8; j++) v[j] = h ? f[j].y : f[j].x;
            float4 s0, s1;
            if (fuse_silu) {
                float4 g0 = *(const float4*)&d_act[off];
                float4 g1 = *(const float4*)&d_act[off + 4];
                s0.x = silu_f(g0.x) * v[0]; s0.y = silu_f(g0.y) * v[1];
                s0.z = silu_f(g0.z) * v[2]; s0.w = silu_f(g0.w) * v[3];
                s1.x = silu_f(g1.x) * v[4]; s1.y = silu_f(g1.y) * v[5];
                s1.z = silu_f(g1.z) * v[6]; s1.w = silu_f(g1.w) * v[7];
            } else {
                s0.x = v[0]; s0.y = v[1]; s0.z = v[2]; s0.w = v[3];
                s1.x = v[4]; s1.y = v[5]; s1.z = v[6]; s1.w = v[7];
            }
            *(float4*)&d_act[off]     = s0;
            *(float4*)&d_act[off + 4] = s1;
        }
    }
}

// ---------------- down GEMM: [count x HDIM] @ [HDIM x DDIM], scatter-add ----
__global__ __launch_bounds__(256, 2)
void down_gemm(const float* __restrict__ Wdstk,
               const float* __restrict__ Wdsh,
               float* __restrict__ out) {
    const int e = blockIdx.z;
    const int count = (e == NEXP) ? NTOK : d_cnt[e];
    const int m0 = blockIdx.y * 128;
    if (m0 >= count) return;
    const int n0 = blockIdx.x * 128;
    const float* Bp = (e == NEXP) ? Wdsh : (Wdstk + (size_t)e * HDIM * DDIM);
    const int rowbase = e * NTOK + m0;

    __shared__ float As[16][132];
    __shared__ float Bs[16][128];
    __shared__ int toks[128];
    __shared__ float ws[128];

    const int tid = threadIdx.x;
    if (tid < 128) {
        toks[tid] = d_row_token[rowbase + tid];
        ws[tid]   = d_row_w[rowbase + tid];
    }

    const int tx = tid & 15;
    const int ty = tid >> 4;
    const int arow = tid >> 1;
    const int akp  = (tid & 1) * 8;
    const int brow = tid >> 4;
    const int bcol = (tid & 15) * 8;

    const float* ar = d_act + (size_t)(rowbase + arow) * HDIM + akp;
    const float* bp = Bp + (size_t)brow * DDIM + n0 + bcol;

    u64 acc[4][8];
#pragma unroll
    for (int i = 0; i < 4; i++)
#pragma unroll
        for (int j = 0; j < 8; j++) acc[i][j] = 0ull;

    for (int k0 = 0; k0 < HDIM; k0 += 16) {
        float4 a0 = *(const float4*)(ar + k0);
        float4 a1 = *(const float4*)(ar + k0 + 4);
        float4 b0 = *(const float4*)(bp + (size_t)k0 * DDIM);
        float4 b1 = *(const float4*)(bp + (size_t)k0 * DDIM + 4);
        __syncthreads();
        As[akp + 0][arow] = a0.x; As[akp + 1][arow] = a0.y;
        As[akp + 2][arow] = a0.z; As[akp + 3][arow] = a0.w;
        As[akp + 4][arow] = a1.x; As[akp + 5][arow] = a1.y;
        As[akp + 6][arow] = a1.z; As[akp + 7][arow] = a1.w;
        *(float4*)&Bs[brow][bcol]     = b0;
        *(float4*)&Bs[brow][bcol + 4] = b1;
        __syncthreads();
#pragma unroll
        for (int kk = 0; kk < 16; kk++) {
            float4 av0 = *(const float4*)&As[kk][ty * 8];
            float4 av1 = *(const float4*)&As[kk][ty * 8 + 4];
            float4 bv0 = *(const float4*)&Bs[kk][tx * 8];
            float4 bv1 = *(const float4*)&Bs[kk][tx * 8 + 4];
            u64 ap[4] = { pack2(av0.x, av0.y), pack2(av0.z, av0.w),
                          pack2(av1.x, av1.y), pack2(av1.z, av1.w) };
            u64 bd[8] = { pack2(bv0.x, bv0.x), pack2(bv0.y, bv0.y),
                          pack2(bv0.z, bv0.z), pack2(bv0.w, bv0.w),
                          pack2(bv1.x, bv1.x), pack2(bv1.y, bv1.y),
                          pack2(bv1.z, bv1.z), pack2(bv1.w, bv1.w) };
#pragma unroll
            for (int i = 0; i < 4; i++)
#pragma unroll
                for (int j = 0; j < 8; j++)
                    acc[i][j] = fma2(ap[i], bd[j], acc[i][j]);
        }
    }

    // epilogue: weighted scatter-add per token row
#pragma unroll
    for (int i = 0; i < 4; i++) {
        float2 f[8];
#pragma unroll
        for (int j = 0; j < 8; j++) f[j] = unpack2(acc[i][j]);
#pragma unroll
        for (int h = 0; h < 2; h++) {
            int m = ty * 8 + i * 2 + h;
            if (m0 + m < count) {
                int t = toks[m];
                float w = ws[m];
                size_t base = (size_t)t * DDIM + n0 + tx * 8;
#pragma unroll
                for (int j = 0; j < 8; j++) {
                    float v = h ? f[j].y : f[j].x;
                    atomicAdd(&out[base + j], w * v);
                }
            }
        }
    }
}

// ---------------- launch -----------------------------------------------------
extern "C" void kernel_launch(void* const* d_in, const int* in_sizes, int n_in,
                              void* d_out, int out_size) {
    const float* x    = (const float*)d_in[0];
    const float* Wg_s = (const float*)d_in[1];
    const float* Wu_s = (const float*)d_in[2];
    const float* Wd_s = (const float*)d_in[3];
    const float* Wg   = (const float*)d_in[4];
    const float* Wu   = (const float*)d_in[5];
    const float* Wd   = (const float*)d_in[6];
    const float* Wr   = (const float*)d_in[7];
    const float* br   = (const float*)d_in[8];
    const float* rb   = (const float*)d_in[9];
    float* out = (float*)d_out;
    (void)in_sizes; (void)n_in;

    cudaMemsetAsync(d_out, 0, (size_t)out_size * sizeof(float), 0);
    init_kernel<<<1, 32>>>();
    router_kernel<<<(NTOK * 32 + 255) / 256, 256>>>(x, Wr, br, rb);

    // 9 "experts": z=0..7 routed, z=8 shared (all tokens)
    dim3 gridGU(HDIM / 128, NTOK / 128, NEXP + 1);   // 11 x 64 x 9
    gu_gemm<<<gridGU, 256>>>(x, Wg, Wg_s, 0);        // G
    gu_gemm<<<gridGU, 256>>>(x, Wu, Wu_s, 1);        // act = silu(G)*U in place

    dim3 gridDN(DDIM / 128, NTOK / 128, NEXP + 1);   // 16 x 64 x 9
    down_gemm<<<gridDN, 256>>>(Wd, Wd_s, out);
}

// round 2
// speedup vs baseline: 1.0004x; 1.0004x over previous
#include <cuda_runtime.h>
#include <cstdint>
#include <math.h>

// Problem constants (fixed by the reference)
#define NTOK 8192      // B*S = 4*2048 tokens
#define DDIM 2048      // embed
#define HDIM 1408      // ffn intermediate
#define NEXP 8         // routed experts; slot 8 = shared expert
#define ROWCAP (9 * NTOK)   // 73728 compact rows (8 routed capacities + shared)

typedef unsigned long long u64;

// ---------------- device scratch (static, allocation-free) ----------------
__device__ int   d_cnt[16];
__device__ int   d_row_token[ROWCAP];
__device__ float d_row_w[ROWCAP];
// activation scratch: gate writes raw G, up-kernel rewrites silu(G)*U in place
__device__ float d_act[(size_t)ROWCAP * HDIM];

// ---------------- packed f32x2 helpers (sm_103a FFMA2 path) ----------------
__device__ __forceinline__ u64 pack2(float lo, float hi) {
    u64 r;
    asm("mov.b64 %0, {%1, %2};" : "=l"(r) : "f"(lo), "f"(hi));
    return r;
}
__device__ __forceinline__ u64 fma2(u64 a, u64 b, u64 c) {
    u64 d;
    asm("fma.rn.f32x2 %0, %1, %2, %3;" : "=l"(d) : "l"(a), "l"(b), "l"(c));
    return d;
}
__device__ __forceinline__ float2 unpack2(u64 v) {
    float2 f;
    asm("mov.b64 {%0, %1}, %2;" : "=f"(f.x), "=f"(f.y) : "l"(v));
    return f;
}

__device__ __forceinline__ float silu_f(float g) {
    return g / (1.f + expf(-g));
}

// ---------------- init: zero per-expert cursors (graph replays!) -----------
__global__ void init_kernel() {
    if (threadIdx.x < 16) d_cnt[threadIdx.x] = 0;
}

// ---------------- router: sigmoid top-2, build compact row lists -----------
__global__ void router_kernel(const float* __restrict__ x,
                              const float* __restrict__ Wr,
                              const float* __restrict__ br,
                              const float* __restrict__ rb) {
    int g = blockIdx.x * blockDim.x + threadIdx.x;
    int t = g >> 5;
    int lane = g & 31;
    if (t >= NTOK) return;

    const float* xr = x + (size_t)t * DDIM;
    float acc[NEXP];
#pragma unroll
    for (int e = 0; e < NEXP; e++) acc[e] = 0.f;

    for (int d = lane; d < DDIM; d += 32) {
        float xv = xr[d];
        const float* wr = Wr + d * NEXP;
#pragma unroll
        for (int e = 0; e < NEXP; e++) acc[e] += xv * wr[e];
    }
#pragma unroll
    for (int off = 16; off > 0; off >>= 1) {
#pragma unroll
        for (int e = 0; e < NEXP; e++)
            acc[e] += __shfl_xor_sync(0xffffffffu, acc[e], off);
    }
    if (lane == 0) {
        float p[NEXP];
#pragma unroll
        for (int e = 0; e < NEXP; e++)
            p[e] = 1.f / (1.f + expf(-(acc[e] + br[e] + rb[e])));
        // top-2, ties -> lowest index first (matches jax.lax.top_k)
        int i0 = 0;
#pragma unroll
        for (int e = 1; e < NEXP; e++) if (p[e] > p[i0]) i0 = e;
        int i1 = (i0 == 0) ? 1 : 0;
#pragma unroll
        for (int e = 0; e < NEXP; e++) if (e != i0 && p[e] > p[i1]) i1 = e;
        float s = p[i0] + p[i1];
        float w0 = p[i0] / s;
        float w1 = p[i1] / s;

        int r0 = atomicAdd(&d_cnt[i0], 1);
        d_row_token[i0 * NTOK + r0] = t;
        d_row_w[i0 * NTOK + r0] = w0;
        int r1 = atomicAdd(&d_cnt[i1], 1);
        d_row_token[i1 * NTOK + r1] = t;
        d_row_w[i1 * NTOK + r1] = w1;
        // shared-expert region: identity rows, weight 1
        d_row_token[NEXP * NTOK + t] = t;
        d_row_w[NEXP * NTOK + t] = 1.f;
    }
}

// ---------------- gate/up GEMM: [count x DDIM] @ [DDIM x HDIM] --------------
// fuse_silu == 0 : write raw G into d_act
// fuse_silu == 1 : read G from d_act, write silu(G) * U back in place
__global__ __launch_bounds__(256, 2)
void gu_gemm(const float* __restrict__ x,
             const float* __restrict__ Bstk,
             const float* __restrict__ Bsh,
             int fuse_silu) {
    const int e = blockIdx.z;
    const int count = (e == NEXP) ? NTOK : d_cnt[e];
    const int m0 = blockIdx.y * 128;
    if (m0 >= count) return;
    const int n0 = blockIdx.x * 128;
    const float* Bp = (e == NEXP) ? Bsh : (Bstk + (size_t)e * DDIM * HDIM);
    const int rowbase = e * NTOK + m0;

    __shared__ float As[16][132];
    __shared__ float Bs[16][128];
    __shared__ int toks[128];

    const int tid = threadIdx.x;
    if (tid < 128) toks[tid] = d_row_token[rowbase + tid];
    __syncthreads();

    const int tx = tid & 15;
    const int ty = tid >> 4;
    const int arow = tid >> 1;
    const int akp  = (tid & 1) * 8;
    const int brow = tid >> 4;
    const int bcol = (tid & 15) * 8;

    const float* xr = x + (size_t)toks[arow] * DDIM + akp;
    const float* bp = Bp + (size_t)brow * HDIM + n0 + bcol;

    u64 acc[4][8];
#pragma unroll
    for (int i = 0; i < 4; i++)
#pragma unroll
        for (int j = 0; j < 8; j++) acc[i][j] = 0ull;

    for (int k0 = 0; k0 < DDIM; k0 += 16) {
        float4 a0 = *(const float4*)(xr + k0);
        float4 a1 = *(const float4*)(xr + k0 + 4);
        float4 b0 = *(const float4*)(bp + (size_t)k0 * HDIM);
        float4 b1 = *(const float4*)(bp + (size_t)k0 * HDIM + 4);
        __syncthreads();
        As[akp + 0][arow] = a0.x; As[akp + 1][arow] = a0.y;
        As[akp + 2][arow] = a0.z; As[akp + 3][arow] = a0.w;
        As[akp + 4][arow] = a1.x; As[akp + 5][arow] = a1.y;
        As[akp + 6][arow] = a1.z; As[akp + 7][arow] = a1.w;
        *(float4*)&Bs[brow][bcol]     = b0;
        *(float4*)&Bs[brow][bcol + 4] = b1;
        __syncthreads();
#pragma unroll
        for (int kk = 0; kk < 16; kk++) {
            float4 av0 = *(const float4*)&As[kk][ty * 8];
            float4 av1 = *(const float4*)&As[kk][ty * 8 + 4];
            float4 bv0 = *(const float4*)&Bs[kk][tx * 8];
            float4 bv1 = *(const float4*)&Bs[kk][tx * 8 + 4];
            u64 ap[4] = { pack2(av0.x, av0.y), pack2(av0.z, av0.w),
                          pack2(av1.x, av1.y), pack2(av1.z, av1.w) };
            u64 bd[8] = { pack2(bv0.x, bv0.x), pack2(bv0.y, bv0.y),
                          pack2(bv0.z, bv0.z), pack2(bv0.w, bv0.w),
                          pack2(bv1.x, bv1.x), pack2(bv1.y, bv1.y),
                          pack2(bv1.z, bv1.z), pack2(bv1.w, bv1.w) };
#pragma unroll
            for (int i = 0; i < 4; i++)
#pragma unroll
                for (int j = 0; j < 8; j++)
                    acc[i][j] = fma2(ap[i], bd[j], acc[i][j]);
        }
    }

    // epilogue
#pragma unroll
    for (int i = 0; i < 4; i++) {
        float2 f[8];
#pragma unroll
        for (int j = 0; j < 8; j++) f[j] = unpack2(acc[i][j]);
#pragma unroll
        for (int h = 0; h < 2; h++) {
            int m = ty * 8 + i * 2 + h;
            size_t off = (size_t)(rowbase + m) * HDIM + n0 + tx * 8;
            float v[8];
#pragma unroll
            for (int j = 0; j < 8; j++) v[j] = h ? f[j].y : f[j].x;
            float4 s0, s1;
            if (fuse_silu) {
                float4 g0 = *(const float4*)&d_act[off];
                float4 g1 = *(const float4*)&d_act[off + 4];
                s0.x = silu_f(g0.x) * v[0]; s0.y = silu_f(g0.y) * v[1];
                s0.z = silu_f(g0.z) * v[2]; s0.w = silu_f(g0.w) * v[3];
                s1.x = silu_f(g1.x) * v[4]; s1.y = silu_f(g1.y) * v[5];
                s1.z = silu_f(g1.z) * v[6]; s1.w = silu_f(g1.w) * v[7];
            } else {
                s0.x = v[0]; s0.y = v[1]; s0.z = v[2]; s0.w = v[3];
                s1.x = v[4]; s1.y = v[5]; s1.z = v[6]; s1.w = v[7];
            }
            *(float4*)&d_act[off]     = s0;
            *(float4*)&d_act[off + 4] = s1;
        }
    }
}

// ---------------- down GEMM: [count x HDIM] @ [HDIM x DDIM], scatter-add ----
__global__ __launch_bounds__(256, 2)
void down_gemm(const float* __restrict__ Wdstk,
               const float* __restrict__ Wdsh,
               float* __restrict__ out) {
    const int e = blockIdx.z;
    const int count = (e == NEXP) ? NTOK : d_cnt[e];
    const int m0 = blockIdx.y * 128;
    if (m0 >= count) return;
    const int n0 = blockIdx.x * 128;
    const float* Bp = (e == NEXP) ? Wdsh : (Wdstk + (size_t)e * HDIM * DDIM);
    const int rowbase = e * NTOK + m0;

    __shared__ float As[16][132];
    __shared__ float Bs[16][128];
    __shared__ int toks[128];
    __shared__ float ws[128];

    const int tid = threadIdx.x;
    if (tid < 128) {
        toks[tid] = d_row_token[rowbase + tid];
        ws[tid]   = d_row_w[rowbase + tid];
    }

    const int tx = tid & 15;
    const int ty = tid >> 4;
    const int arow = tid >> 1;
    const int akp  = (tid & 1) * 8;
    const int brow = tid >> 4;
    const int bcol = (tid & 15) * 8;

    const float* ar = d_act + (size_t)(rowbase + arow) * HDIM + akp;
    const float* bp = Bp + (size_t)brow * DDIM + n0 + bcol;

    u64 acc[4][8];
#pragma unroll
    for (int i = 0; i < 4; i++)
#pragma unroll
        for (int j = 0; j < 8; j++) acc[i][j] = 0ull;

    for (int k0 = 0; k0 < HDIM; k0 += 16) {
        float4 a0 = *(const float4*)(ar + k0);
        float4 a1 = *(const float4*)(ar + k0 + 4);
        float4 b0 = *(const float4*)(bp + (size_t)k0 * DDIM);
        float4 b1 = *(const float4*)(bp + (size_t)k0 * DDIM + 4);
        __syncthreads();
        As[akp + 0][arow] = a0.x; As[akp + 1][arow] = a0.y;
        As[akp + 2][arow] = a0.z; As[akp + 3][arow] = a0.w;
        As[akp + 4][arow] = a1.x; As[akp + 5][arow] = a1.y;
        As[akp + 6][arow] = a1.z; As[akp + 7][arow] = a1.w;
        *(float4*)&Bs[brow][bcol]     = b0;
        *(float4*)&Bs[brow][bcol + 4] = b1;
        __syncthreads();
#pragma unroll
        for (int kk = 0; kk < 16; kk++) {
            float4 av0 = *(const float4*)&As[kk][ty * 8];
            float4 av1 = *(const float4*)&As[kk][ty * 8 + 4];
            float4 bv0 = *(const float4*)&Bs[kk][tx * 8];
            float4 bv1 = *(const float4*)&Bs[kk][tx * 8 + 4];
            u64 ap[4] = { pack2(av0.x, av0.y), pack2(av0.z, av0.w),
                          pack2(av1.x, av1.y), pack2(av1.z, av1.w) };
            u64 bd[8] = { pack2(bv0.x, bv0.x), pack2(bv0.y, bv0.y),
                          pack2(bv0.z, bv0.z), pack2(bv0.w, bv0.w),
                          pack2(bv1.x, bv1.x), pack2(bv1.y, bv1.y),
                          pack2(bv1.z, bv1.z), pack2(bv1.w, bv1.w) };
#pragma unroll
            for (int i = 0; i < 4; i++)
#pragma unroll
                for (int j = 0; j < 8; j++)
                    acc[i][j] = fma2(ap[i], bd[j], acc[i][j]);
        }
    }

    // epilogue: weighted scatter-add per token row
#pragma unroll
    for (int i = 0; i < 4; i++) {
        float2 f[8];
#pragma unroll
        for (int j = 0; j < 8; j++) f[j] = unpack2(acc[i][j]);
#pragma unroll
        for (int h = 0; h < 2; h++) {
            int m = ty * 8 + i * 2 + h;
            if (m0 + m < count) {
                int t = toks[m];
                float w = ws[m];
                size_t base = (size_t)t * DDIM + n0 + tx * 8;
#pragma unroll
                for (int j = 0; j < 8; j++) {
                    float v = h ? f[j].y : f[j].x;
                    atomicAdd(&out[base + j], w * v);
                }
            }
        }
    }
}

// ---------------- launch -----------------------------------------------------
extern "C" void kernel_launch(void* const* d_in, const int* in_sizes, int n_in,
                              void* d_out, int out_size) {
    const float* x    = (const float*)d_in[0];
    const float* Wg_s = (const float*)d_in[1];
    const float* Wu_s = (const float*)d_in[2];
    const float* Wd_s = (const float*)d_in[3];
    const float* Wg   = (const float*)d_in[4];
    const float* Wu   = (const float*)d_in[5];
    const float* Wd   = (const float*)d_in[6];
    const float* Wr   = (const float*)d_in[7];
    const float* br   = (const float*)d_in[8];
    const float* rb   = (const float*)d_in[9];
    float* out = (float*)d_out;
    (void)in_sizes; (void)n_in;

    cudaMemsetAsync(d_out, 0, (size_t)out_size * sizeof(float), 0);
    init_kernel<<<1, 32>>>();
    router_kernel<<<(NTOK * 32 + 255) / 256, 256>>>(x, Wr, br, rb);

    // 9 "experts": z=0..7 routed, z=8 shared (all tokens)
    dim3 gridGU(HDIM / 128, NTOK / 128, NEXP + 1);   // 11 x 64 x 9
    gu_gemm<<<gridGU, 256>>>(x, Wg, Wg_s, 0);        // G
    gu_gemm<<<gridGU, 256>>>(x, Wu, Wu_s, 1);        // act = silu(G)*U in place

    dim3 gridDN(DDIM / 128, NTOK / 128, NEXP + 1);   // 16 x 64 x 9
    down_gemm<<<gridDN, 256>>>(Wd, Wd_s, out);
}

// round 5
// speedup vs baseline: 3.0559x; 3.0548x over previous
#include <cuda_runtime.h>
#include <cuda_bf16.h>
#include <cstdint>
#include <math.h>

#define NTOK 8192
#define DDIM 2048
#define HDIM 1408
#define NEXP 8
#define KBLK_D  32
#define KBLK_H  22
#define NBLK_GU 11
#define NBLK_DN 16
#define RBLKS   576
#define TILE_E  8192
#define TILE_B  16384

typedef unsigned int u32;
typedef unsigned long long u64b;

__device__ __host__ __forceinline__ u32 SWZ(u32 x) { return x ^ ((x >> 3) & 0x70); }

// ---------------- static device scratch ----------------
__device__ int   d_cnt[16];
__device__ int   d_row_token[9 * NTOK];
__device__ int   d_tok_idx[2 * NTOK];
__device__ float d_tok_wt[2 * NTOK];
__device__ __align__(1024) __nv_bfloat16 d_xg_hi[(size_t)RBLKS * KBLK_D * TILE_E];
__device__ __align__(1024) __nv_bfloat16 d_xg_lo[(size_t)RBLKS * KBLK_D * TILE_E];
__device__ __align__(1024) __nv_bfloat16 d_wg_hi[(size_t)9 * NBLK_GU * KBLK_D * TILE_E];
__device__ __align__(1024) __nv_bfloat16 d_wg_lo[(size_t)9 * NBLK_GU * KBLK_D * TILE_E];
__device__ __align__(1024) __nv_bfloat16 d_wu_hi[(size_t)9 * NBLK_GU * KBLK_D * TILE_E];
__device__ __align__(1024) __nv_bfloat16 d_wu_lo[(size_t)9 * NBLK_GU * KBLK_D * TILE_E];
__device__ __align__(1024) __nv_bfloat16 d_wd_hi[(size_t)9 * NBLK_DN * KBLK_H * TILE_E];
__device__ __align__(1024) __nv_bfloat16 d_wd_lo[(size_t)9 * NBLK_DN * KBLK_H * TILE_E];
__device__ __align__(1024) __nv_bfloat16 d_act_hi[(size_t)RBLKS * KBLK_H * TILE_E];
__device__ __align__(1024) __nv_bfloat16 d_act_lo[(size_t)RBLKS * KBLK_H * TILE_E];
__device__ __align__(1024) float d_y[(size_t)9 * NTOK * DDIM];

// ---------------- PTX helpers (baseline compute_103 only) ----------------
__device__ __forceinline__ u32 smem_u32(const void* p) {
    u32 a;
    asm("{ .reg .u64 t; cvta.to.shared.u64 t, %1; cvt.u32.u64 %0, t; }" : "=r"(a) : "l"(p));
    return a;
}
#define MBARRIER_INIT(a, c) \
    asm volatile("mbarrier.init.shared.b64 [%0], %1;" :: "r"((u32)(a)), "r"((u32)(c)) : "memory")
#define MBARRIER_EXPECT_TX(a, b) \
    asm volatile("mbarrier.arrive.expect_tx.shared.b64 _, [%0], %1;" :: "r"((u32)(a)), "r"((u32)(b)) : "memory")
#define MBAR_WAIT_ACQ(mbar, parity) do {                                         \
    u32 _m = (u32)(mbar); u32 _p = (u32)(parity); u32 _d;                        \
    asm volatile("{\n\t.reg .pred p;\n\t"                                        \
        "mbarrier.try_wait.parity.acquire.cta.shared::cta.b64 p, [%1], %2;\n\t"  \
        "selp.b32 %0, 1, 0, p;\n\t}" : "=r"(_d) : "r"(_m), "r"(_p) : "memory");  \
    if (!_d) {                                                                   \
        asm volatile("{\n\t.reg .pred P1;\n\t"                                   \
            "WL%=:\n\t"                                                          \
            "mbarrier.try_wait.parity.acquire.cta.shared::cta.b64 P1, [%0], %1, 0x989680;\n\t" \
            "@P1 bra.uni WD%=;\n\t"                                              \
            "bra.uni WL%=;\n\tWD%=:\n\t}" :: "r"(_m), "r"(_p) : "memory");       \
    }                                                                            \
} while (0)

__device__ __forceinline__ void bulk_g2s(u32 dst, const void* src, u32 bytes, u32 mbar) {
    asm volatile("cp.async.bulk.shared::cluster.global.mbarrier::complete_tx::bytes [%0], [%1], %2, [%3];"
        :: "r"(dst), "l"(src), "r"(bytes), "r"(mbar) : "memory");
}

__device__ __forceinline__ void ldsm4(u32& r0, u32& r1, u32& r2, u32& r3, u32 addr) {
    asm volatile("ldmatrix.sync.aligned.m8n8.x4.shared.b16 {%0,%1,%2,%3}, [%4];"
        : "=r"(r0), "=r"(r1), "=r"(r2), "=r"(r3) : "r"(addr));
}
__device__ __forceinline__ void mma16816(float* c, u32 a0, u32 a1, u32 a2, u32 a3, u32 b0, u32 b1) {
    asm volatile("mma.sync.aligned.m16n8k16.row.col.f32.bf16.bf16.f32 "
        "{%0,%1,%2,%3}, {%4,%5,%6,%7}, {%8,%9}, {%0,%1,%2,%3};"
        : "+f"(c[0]), "+f"(c[1]), "+f"(c[2]), "+f"(c[3])
        : "r"(a0), "r"(a1), "r"(a2), "r"(a3), "r"(b0), "r"(b1));
}

__device__ __forceinline__ u32 split_pair(float v0, float v1, u32& lo_out) {
    __nv_bfloat16 h0 = __float2bfloat16_rn(v0);
    __nv_bfloat16 h1 = __float2bfloat16_rn(v1);
    __nv_bfloat16 l0 = __float2bfloat16_rn(v0 - __bfloat162float(h0));
    __nv_bfloat16 l1 = __float2bfloat16_rn(v1 - __bfloat162float(h1));
    lo_out = ((u32)__bfloat16_as_ushort(l1) << 16) | (u32)__bfloat16_as_ushort(l0);
    return ((u32)__bfloat16_as_ushort(h1) << 16) | (u32)__bfloat16_as_ushort(h0);
}
__device__ __forceinline__ float silu_f(float g) { return g / (1.f + expf(-g)); }

// ---------------- init + router ----------------
__global__ void init_kernel() { if (threadIdx.x < 16) d_cnt[threadIdx.x] = 0; }

__global__ void router_kernel(const float* __restrict__ x, const float* __restrict__ Wr,
                              const float* __restrict__ br, const float* __restrict__ rb) {
    int g = blockIdx.x * blockDim.x + threadIdx.x;
    int t = g >> 5, lane = g & 31;
    if (t >= NTOK) return;
    const float* xr = x + (size_t)t * DDIM;
    float acc[NEXP];
#pragma unroll
    for (int e = 0; e < NEXP; e++) acc[e] = 0.f;
    for (int d = lane; d < DDIM; d += 32) {
        float xv = xr[d];
        const float* wr = Wr + d * NEXP;
#pragma unroll
        for (int e = 0; e < NEXP; e++) acc[e] += xv * wr[e];
    }
#pragma unroll
    for (int off = 16; off > 0; off >>= 1)
#pragma unroll
        for (int e = 0; e < NEXP; e++) acc[e] += __shfl_xor_sync(0xffffffffu, acc[e], off);
    if (lane == 0) {
        float p[NEXP];
#pragma unroll
        for (int e = 0; e < NEXP; e++) p[e] = 1.f / (1.f + expf(-(acc[e] + br[e] + rb[e])));
        int i0 = 0;
#pragma unroll
        for (int e = 1; e < NEXP; e++) if (p[e] > p[i0]) i0 = e;
        int i1 = (i0 == 0) ? 1 : 0;
#pragma unroll
        for (int e = 0; e < NEXP; e++) if (e != i0 && p[e] > p[i1]) i1 = e;
        float s = p[i0] + p[i1];
        int r0 = atomicAdd(&d_cnt[i0], 1);
        d_row_token[i0 * NTOK + r0] = t;
        int r1 = atomicAdd(&d_cnt[i1], 1);
        d_row_token[i1 * NTOK + r1] = t;
        d_row_token[NEXP * NTOK + t] = t;
        d_tok_idx[2 * t] = i0 * NTOK + r0;
        d_tok_idx[2 * t + 1] = i1 * NTOK + r1;
        d_tok_wt[2 * t] = p[i0] / s;
        d_tok_wt[2 * t + 1] = p[i1] / s;
    }
}

// ---------------- weight convert: transpose + split into SW128 tiles --------
__global__ void conv_w_kernel(const float* __restrict__ Wstk, const float* __restrict__ Wsh,
                              int sel, int Kdim, int Ndim, int nblk, int kblk) {
    int kb = blockIdx.x, nb = blockIdx.y, e = blockIdx.z;
    const float* src = (e == NEXP) ? Wsh : (Wstk + (size_t)e * Kdim * Ndim);
    __shared__ float s[64][129];
    int n0 = nb * 128, k0 = kb * 64;
    for (int i = threadIdx.x; i < 64 * 128; i += 256) {
        int kk = i >> 7, nn = i & 127;
        s[kk][nn] = src[(size_t)(k0 + kk) * Ndim + n0 + nn];
    }
    __syncthreads();
    size_t tb = ((size_t)(e * nblk + nb) * kblk + kb) * TILE_E;
    char* th = (char*)((sel == 0 ? d_wg_hi : sel == 1 ? d_wu_hi : d_wd_hi) + tb);
    char* tl = (char*)((sel == 0 ? d_wg_lo : sel == 1 ? d_wu_lo : d_wd_lo) + tb);
    int lane = threadIdx.x & 31, w = threadIdx.x >> 5;
    for (int nn = w; nn < 128; nn += 8) {
        u32 lo, hi = split_pair(s[2 * lane][nn], s[2 * lane + 1][nn], lo);
        u32 off = SWZ(nn * 128 + lane * 4);
        *(u32*)(th + off) = hi;
        *(u32*)(tl + off) = lo;
    }
}

// ---------------- gather x rows + split into SW128 tiles ----------------
__global__ void conv_x_kernel(const float* __restrict__ x) {
    int kb = blockIdx.x, rb = blockIdx.y;
    int e = rb >> 6, r0 = (rb & 63) * 128;
    int count = (e == NEXP) ? NTOK : d_cnt[e];
    if (r0 >= count) return;
    size_t tb = ((size_t)rb * KBLK_D + kb) * TILE_E;
    char* th = (char*)(d_xg_hi + tb);
    char* tl = (char*)(d_xg_lo + tb);
    int lane = threadIdx.x & 31, w = threadIdx.x >> 5;
    for (int rr = w; rr < 128; rr += 8) {
        if (r0 + rr >= count) continue;
        int tok = d_row_token[e * NTOK + r0 + rr];
        float2 v = *(const float2*)(x + (size_t)tok * DDIM + kb * 64 + lane * 2);
        u32 lo, hi = split_pair(v.x, v.y, lo);
        u32 off = SWZ(rr * 128 + lane * 4);
        *(u32*)(th + off) = hi;
        *(u32*)(tl + off) = lo;
    }
}

// ---------------- fused gate+up GEMM (mma.sync bf16x3) ----------------
// CTA: M=128 (rowblock by), N=64 (nb of 22). Warps 0-3: G, 4-7: U; each 64x32.
#define GU_S 2
#define GU_STG 65536
__global__ __launch_bounds__(256, 1) void gu_kernel() {
    int nb = blockIdx.x, by = blockIdx.y, e = blockIdx.z;
    int count = (e == NEXP) ? NTOK : d_cnt[e];
    if (by * 128 >= count) return;

    extern __shared__ __align__(16) char dyn[];
    __shared__ __align__(8) u64b mbar[GU_S];
    u32 buf0 = (smem_u32(dyn) + 1023) & ~1023u;
    u32 mb = smem_u32(mbar);
    int tid = threadIdx.x, lane = tid & 31, wid = tid >> 5;

    if (tid == 0)
        for (int i = 0; i < GU_S; i++) MBARRIER_INIT(mb + 8 * i, 1);
    __syncthreads();

    int rb = e * 64 + by;
    size_t abase = (size_t)rb * KBLK_D * TILE_E;
    size_t wbase = (size_t)(e * NBLK_GU + (nb >> 1)) * KBLK_D * TILE_E;
    int half = (nb & 1) * 4096;  // elems (64 rows x 128B)

    if (tid == 0) {
#pragma unroll
        for (int s = 0; s < GU_S; s++) {
            u32 fb = mb + 8 * s;
            MBARRIER_EXPECT_TX(fb, GU_STG);
            u32 dst = buf0 + s * GU_STG;
            size_t so = (size_t)s * TILE_E;
            bulk_g2s(dst,         d_xg_hi + abase + so, 16384, fb);
            bulk_g2s(dst + 16384, d_xg_lo + abase + so, 16384, fb);
            bulk_g2s(dst + 32768, d_wg_hi + wbase + so + half, 8192, fb);
            bulk_g2s(dst + 40960, d_wg_lo + wbase + so + half, 8192, fb);
            bulk_g2s(dst + 49152, d_wu_hi + wbase + so + half, 8192, fb);
            bulk_g2s(dst + 57344, d_wu_lo + wbase + so + half, 8192, fb);
        }
    }

    int w2 = wid & 3;
    int wm = w2 & 1, wn = w2 >> 1;
    bool isG = wid < 4;
    int arow = wm * 64 + (lane & 15);
    u32 akoff = (lane >> 4) * 16;
    int nrow = wn * 32 + ((lane >> 4) << 3) + (lane & 7);
    u32 bkoff = ((lane >> 3) & 1) * 16;

    float acc[4][4][4];
#pragma unroll
    for (int i = 0; i < 4; i++)
#pragma unroll
        for (int n = 0; n < 4; n++)
#pragma unroll
            for (int q = 0; q < 4; q++) acc[i][n][q] = 0.f;

    for (int s = 0; s < KBLK_D; s++) {
        int b = s % GU_S, ph = (s / GU_S) & 1;
        MBAR_WAIT_ACQ(mb + 8 * b, ph);
        u32 st = buf0 + b * GU_STG;
        u32 Ah = st, Al = st + 16384;
        u32 Bh = isG ? (st + 32768) : (st + 49152);
        u32 Bl = Bh + 8192;

        for (int j = 0; j < 4; j++) {
            u32 ah[4][4], al[4][4];
#pragma unroll
            for (int i = 0; i < 4; i++) {
                u32 off = SWZ((u32)(arow + i * 16) * 128 + j * 32 + akoff);
                ldsm4(ah[i][0], ah[i][1], ah[i][2], ah[i][3], Ah + off);
                ldsm4(al[i][0], al[i][1], al[i][2], al[i][3], Al + off);
            }
            u32 bh[8], bl[8];
#pragma unroll
            for (int p = 0; p < 2; p++) {
                u32 off = SWZ((u32)(nrow + p * 16) * 128 + j * 32 + bkoff);
                ldsm4(bh[4 * p], bh[4 * p + 1], bh[4 * p + 2], bh[4 * p + 3], Bh + off);
                ldsm4(bl[4 * p], bl[4 * p + 1], bl[4 * p + 2], bl[4 * p + 3], Bl + off);
            }
#pragma unroll
            for (int i = 0; i < 4; i++)
#pragma unroll
                for (int n = 0; n < 4; n++) {
                    mma16816(acc[i][n], ah[i][0], ah[i][1], ah[i][2], ah[i][3], bh[2 * n], bh[2 * n + 1]);
                    mma16816(acc[i][n], ah[i][0], ah[i][1], ah[i][2], ah[i][3], bl[2 * n], bl[2 * n + 1]);
                    mma16816(acc[i][n], al[i][0], al[i][1], al[i][2], al[i][3], bh[2 * n], bh[2 * n + 1]);
                }
        }
        __syncthreads();
        if (tid == 0 && s + GU_S < KBLK_D) {
            int ns = s + GU_S;
            u32 fb = mb + 8 * b;
            MBARRIER_EXPECT_TX(fb, GU_STG);
            u32 dst = buf0 + b * GU_STG;
            size_t so = (size_t)ns * TILE_E;
            bulk_g2s(dst,         d_xg_hi + abase + so, 16384, fb);
            bulk_g2s(dst + 16384, d_xg_lo + abase + so, 16384, fb);
            bulk_g2s(dst + 32768, d_wg_hi + wbase + so + half, 8192, fb);
            bulk_g2s(dst + 40960, d_wg_lo + wbase + so + half, 8192, fb);
            bulk_g2s(dst + 49152, d_wu_hi + wbase + so + half, 8192, fb);
            bulk_g2s(dst + 57344, d_wu_lo + wbase + so + half, 8192, fb);
        }
    }

    // ---- epilogue: exchange U through SMEM, act = silu(G)*U ----
    float* ex = (float*)dyn;   // 128 x 66 f32
    __syncthreads();
    if (!isG) {
#pragma unroll
        for (int i = 0; i < 4; i++)
#pragma unroll
            for (int n = 0; n < 4; n++) {
                int r0 = wm * 64 + i * 16 + (lane >> 2);
                int c = wn * 32 + n * 8 + 2 * (lane & 3);
                *(float2*)&ex[r0 * 66 + c] = make_float2(acc[i][n][0], acc[i][n][1]);
                *(float2*)&ex[(r0 + 8) * 66 + c] = make_float2(acc[i][n][2], acc[i][n][3]);
            }
    }
    __syncthreads();
    if (isG) {
        char* th = (char*)(d_act_hi + ((size_t)rb * KBLK_H + nb) * TILE_E);
        char* tl = (char*)(d_act_lo + ((size_t)rb * KBLK_H + nb) * TILE_E);
#pragma unroll
        for (int i = 0; i < 4; i++)
#pragma unroll
            for (int n = 0; n < 4; n++) {
                int r0 = wm * 64 + i * 16 + (lane >> 2);
                int c = wn * 32 + n * 8 + 2 * (lane & 3);
                float2 u0 = *(float2*)&ex[r0 * 66 + c];
                float2 u1 = *(float2*)&ex[(r0 + 8) * 66 + c];
                float a00 = silu_f(acc[i][n][0]) * u0.x;
                float a01 = silu_f(acc[i][n][1]) * u0.y;
                float a10 = silu_f(acc[i][n][2]) * u1.x;
                float a11 = silu_f(acc[i][n][3]) * u1.y;
                u32 lo0, hi0 = split_pair(a00, a01, lo0);
                u32 lo1, hi1 = split_pair(a10, a11, lo1);
                u32 o0 = SWZ((u32)r0 * 128 + c * 2);
                u32 o1 = SWZ((u32)(r0 + 8) * 128 + c * 2);
                *(u32*)(th + o0) = hi0; *(u32*)(tl + o0) = lo0;
                *(u32*)(th + o1) = hi1; *(u32*)(tl + o1) = lo1;
            }
    }
}

// ---------------- down GEMM (mma.sync bf16x3) ----------------
// CTA: M=128, N=64 (nb of 32). 8 warps: 4(M) x 2(N), warp = 32x32.
#define DN_S 3
#define DN_STG 49152
__global__ __launch_bounds__(256, 1) void dn_kernel() {
    int nb = blockIdx.x, by = blockIdx.y, e = blockIdx.z;
    int count = (e == NEXP) ? NTOK : d_cnt[e];
    if (by * 128 >= count) return;

    extern __shared__ __align__(16) char dyn[];
    __shared__ __align__(8) u64b mbar[DN_S];
    u32 buf0 = (smem_u32(dyn) + 1023) & ~1023u;
    u32 mb = smem_u32(mbar);
    int tid = threadIdx.x, lane = tid & 31, wid = tid >> 5;

    if (tid == 0)
        for (int i = 0; i < DN_S; i++) MBARRIER_INIT(mb + 8 * i, 1);
    __syncthreads();

    int rb = e * 64 + by;
    size_t abase = (size_t)rb * KBLK_H * TILE_E;
    size_t wbase = (size_t)(e * NBLK_DN + (nb >> 1)) * KBLK_H * TILE_E;
    int half = (nb & 1) * 4096;

    if (tid == 0) {
#pragma unroll
        for (int s = 0; s < DN_S; s++) {
            u32 fb = mb + 8 * s;
            MBARRIER_EXPECT_TX(fb, DN_STG);
            u32 dst = buf0 + s * DN_STG;
            size_t so = (size_t)s * TILE_E;
            bulk_g2s(dst,         d_act_hi + abase + so, 16384, fb);
            bulk_g2s(dst + 16384, d_act_lo + abase + so, 16384, fb);
            bulk_g2s(dst + 32768, d_wd_hi + wbase + so + half, 8192, fb);
            bulk_g2s(dst + 40960, d_wd_lo + wbase + so + half, 8192, fb);
        }
    }

    int wm = wid & 3, wn = wid >> 2;
    int arow = wm * 32 + (lane & 15);
    u32 akoff = (lane >> 4) * 16;
    int nrow = wn * 32 + ((lane >> 4) << 3) + (lane & 7);
    u32 bkoff = ((lane >> 3) & 1) * 16;

    float acc[2][4][4];
#pragma unroll
    for (int i = 0; i < 2; i++)
#pragma unroll
        for (int n = 0; n < 4; n++)
#pragma unroll
            for (int q = 0; q < 4; q++) acc[i][n][q] = 0.f;

    for (int s = 0; s < KBLK_H; s++) {
        int b = s % DN_S, ph = (s / DN_S) & 1;
        MBAR_WAIT_ACQ(mb + 8 * b, ph);
        u32 st = buf0 + b * DN_STG;
        u32 Ah = st, Al = st + 16384, Bh = st + 32768, Bl = st + 40960;

        for (int j = 0; j < 4; j++) {
            u32 ah[2][4], al[2][4];
#pragma unroll
            for (int i = 0; i < 2; i++) {
                u32 off = SWZ((u32)(arow + i * 16) * 128 + j * 32 + akoff);
                ldsm4(ah[i][0], ah[i][1], ah[i][2], ah[i][3], Ah + off);
                ldsm4(al[i][0], al[i][1], al[i][2], al[i][3], Al + off);
            }
            u32 bh[8], bl[8];
#pragma unroll
            for (int p = 0; p < 2; p++) {
                u32 off = SWZ((u32)(nrow + p * 16) * 128 + j * 32 + bkoff);
                ldsm4(bh[4 * p], bh[4 * p + 1], bh[4 * p + 2], bh[4 * p + 3], Bh + off);
                ldsm4(bl[4 * p], bl[4 * p + 1], bl[4 * p + 2], bl[4 * p + 3], Bl + off);
            }
#pragma unroll
            for (int i = 0; i < 2; i++)
#pragma unroll
                for (int n = 0; n < 4; n++) {
                    mma16816(acc[i][n], ah[i][0], ah[i][1], ah[i][2], ah[i][3], bh[2 * n], bh[2 * n + 1]);
                    mma16816(acc[i][n], ah[i][0], ah[i][1], ah[i][2], ah[i][3], bl[2 * n], bl[2 * n + 1]);
                    mma16816(acc[i][n], al[i][0], al[i][1], al[i][2], al[i][3], bh[2 * n], bh[2 * n + 1]);
                }
        }
        __syncthreads();
        if (tid == 0 && s + DN_S < KBLK_H) {
            int ns = s + DN_S;
            u32 fb = mb + 8 * b;
            MBARRIER_EXPECT_TX(fb, DN_STG);
            u32 dst = buf0 + b * DN_STG;
            size_t so = (size_t)ns * TILE_E;
            bulk_g2s(dst,         d_act_hi + abase + so, 16384, fb);
            bulk_g2s(dst + 16384, d_act_lo + abase + so, 16384, fb);
            bulk_g2s(dst + 32768, d_wd_hi + wbase + so + half, 8192, fb);
            bulk_g2s(dst + 40960, d_wd_lo + wbase + so + half, 8192, fb);
        }
    }

    // epilogue: write raw y rows (fp32)
    float* yb = d_y + ((size_t)(e * NTOK + by * 128)) * DDIM + nb * 64;
#pragma unroll
    for (int i = 0; i < 2; i++)
#pragma unroll
        for (int n = 0; n < 4; n++) {
            int r0 = wm * 32 + i * 16 + (lane >> 2);
            int c = wn * 32 + n * 8 + 2 * (lane & 3);
            *(float2*)&yb[(size_t)r0 * DDIM + c] = make_float2(acc[i][n][0], acc[i][n][1]);
            *(float2*)&yb[(size_t)(r0 + 8) * DDIM + c] = make_float2(acc[i][n][2], acc[i][n][3]);
        }
}

// ---------------- combine: out = y_shared + w0*y0 + w1*y1 ----------------
__global__ void combine_kernel(float* __restrict__ out) {
    int t = blockIdx.x;
    int i0 = d_tok_idx[2 * t], i1 = d_tok_idx[2 * t + 1];
    float w0 = d_tok_wt[2 * t], w1 = d_tok_wt[2 * t + 1];
    const float4* ys = (const float4*)(d_y + ((size_t)(NEXP * NTOK) + t) * DDIM);
    const float4* y0 = (const float4*)(d_y + (size_t)i0 * DDIM);
    const float4* y1 = (const float4*)(d_y + (size_t)i1 * DDIM);
    float4* o = (float4*)(out + (size_t)t * DDIM);
    for (int j = threadIdx.x; j < DDIM / 4; j += blockDim.x) {
        float4 a = ys[j], b = y0[j], c = y1[j];
        float4 r;
        r.x = a.x + w0 * b.x + w1 * c.x;
        r.y = a.y + w0 * b.y + w1 * c.y;
        r.z = a.z + w0 * b.z + w1 * c.z;
        r.w = a.w + w0 * b.w + w1 * c.w;
        o[j] = r;
    }
}

// ---------------- launch ----------------
extern "C" void kernel_launch(void* const* d_in, const int* in_sizes, int n_in,
                              void* d_out, int out_size) {
    const float* x    = (const float*)d_in[0];
    const float* Wg_s = (const float*)d_in[1];
    const float* Wu_s = (const float*)d_in[2];
    const float* Wd_s = (const float*)d_in[3];
    const float* Wg   = (const float*)d_in[4];
    const float* Wu   = (const float*)d_in[5];
    const float* Wd   = (const float*)d_in[6];
    const float* Wr   = (const float*)d_in[7];
    const float* br   = (const float*)d_in[8];
    const float* rb   = (const float*)d_in[9];
    (void)in_sizes; (void)n_in; (void)out_size;

    const int GU_SMEM = 1024 + GU_S * GU_STG;   // 132096
    const int DN_SMEM = 1024 + DN_S * DN_STG;   // 148480
    cudaFuncSetAttribute(gu_kernel, cudaFuncAttributeMaxDynamicSharedMemorySize, GU_SMEM);
    cudaFuncSetAttribute(dn_kernel, cudaFuncAttributeMaxDynamicSharedMemorySize, DN_SMEM);

    init_kernel<<<1, 32>>>();
    router_kernel<<<(NTOK * 32 + 255) / 256, 256>>>(x, Wr, br, rb);

    conv_w_kernel<<<dim3(KBLK_D, NBLK_GU, 9), 256>>>(Wg, Wg_s, 0, DDIM, HDIM, NBLK_GU, KBLK_D);
    conv_w_kernel<<<dim3(KBLK_D, NBLK_GU, 9), 256>>>(Wu, Wu_s, 1, DDIM, HDIM, NBLK_GU, KBLK_D);
    conv_w_kernel<<<dim3(KBLK_H, NBLK_DN, 9), 256>>>(Wd, Wd_s, 2, HDIM, DDIM, NBLK_DN, KBLK_H);
    conv_x_kernel<<<dim3(KBLK_D, RBLKS), 256>>>(x);

    gu_kernel<<<dim3(22, 64, 9), 256, GU_SMEM>>>();
    dn_kernel<<<dim3(32, 64, 9), 256, DN_SMEM>>>();
    combine_kernel<<<NTOK, 256>>>((float*)d_out);
}